// round 9
// baseline (speedup 1.0000x reference)
#include <cuda_runtime.h>

// Problem constants: B=8, N=2048, D=768, two tensors -> 16 (tensor,batch) groups
#define DDIM     768
#define NROWS    32768          // 2*8*2048 source rows
#define NGROUPS  16             // groups of 2048 rows; 16 MB output per group
#define ROW4     512            // float4 per output row
#define NREADER  256            // reader blocks (bids 0..255)
#define NBLOCKS  1024

__device__ float    g_src[NROWS];
__device__ float    g_dst[NROWS];
__device__ unsigned g_cnt[NGROUPS];   // rows published per group (target 2048)

__global__ void edge_reset() {
    if (threadIdx.x < NGROUPS) g_cnt[threadIdx.x] = 0;
}

__global__ __launch_bounds__(256) void edge_fused(
    const float* __restrict__ H,
    const float* __restrict__ Dh,
    const float* __restrict__ W,     // [2*DDIM]: wa then wb
    const float* __restrict__ bptr,  // [1]
    float4* __restrict__ out)
{
    const int tid = threadIdx.x;
    const int bid = blockIdx.x;

    // ---------------- Reader role: bids 0..255 ----------------
    // 256 blocks * 8 warps = 2048 warps -> one row per warp per group pass.
    // Group-major order => group g fully published at ~(g+1) * ~1.2us.
    if (bid < NREADER) {
        int wid  = tid >> 5;
        int lane = tid & 31;
        const float4* Wa4 = (const float4*)W;
        const float4* Wb4 = (const float4*)(W + DDIM);
        float bias = __ldg(bptr);

        for (int g = 0; g < NGROUPS; g++) {
            int r = g * 2048 + bid * 8 + wid;
            const float* X = (r < NROWS / 2) ? (H  + (size_t)r * DDIM)
                                             : (Dh + (size_t)(r - NROWS / 2) * DDIM);
            const float4* X4 = (const float4*)X;
            float sa = 0.f, sb = 0.f;
            #pragma unroll
            for (int k = 0; k < 6; k++) {
                int idx = lane + k * 32;
                float4 x  = __ldcs(&X4[idx]);
                float4 wa = __ldg(&Wa4[idx]);
                float4 wb = __ldg(&Wb4[idx]);
                sa = fmaf(x.x, wa.x, fmaf(x.y, wa.y, fmaf(x.z, wa.z, fmaf(x.w, wa.w, sa))));
                sb = fmaf(x.x, wb.x, fmaf(x.y, wb.y, fmaf(x.z, wb.z, fmaf(x.w, wb.w, sb))));
            }
            #pragma unroll
            for (int off = 16; off; off >>= 1) {
                sa += __shfl_xor_sync(0xffffffffu, sa, off);
                sb += __shfl_xor_sync(0xffffffffu, sb, off);
            }
            if (lane == 0) {
                g_src[r] = sa + bias;
                g_dst[r] = sb;
                __threadfence();                  // release: s-values -> L2 before count
                atomicAdd(&g_cnt[g], 1u);
            }
        }
    }

    // ---------------- Writer role: all 1024 blocks ----------------
    // Static chunk columns: pure writers (bid>=256) own columns 0..767 so
    // group-0 stores begin almost immediately; readers take columns 768..1023
    // after their read pass (all groups ready by then).
    int col = (bid < NREADER) ? (NBLOCKS - NREADER + bid) : (bid - NREADER);

    const float*  src  = g_src;
    const float4* dst4 = (const float4*)g_dst;

    #pragma unroll 1
    for (int g = 0; g < NGROUPS; g++) {           // block's g-th chunk lies in group g
        if (tid == 0) {
            volatile unsigned* p = &g_cnt[g];
            while (*p < 2048u) __nanosleep(128);
            __threadfence();                      // acquire
        }
        __syncthreads();                          // loads below cannot be hoisted past this

        unsigned base = ((unsigned)g * 1024u + (unsigned)col) * 1024u;  // float4 offset
        #pragma unroll
        for (int it = 0; it < 4; it++) {
            unsigned v   = base + it * 256u + tid;
            unsigned row = v >> 9;                // 2 rows per 16KB chunk
            unsigned j4  = v & (ROW4 - 1);
            // .cg: always reads L2 (coherent with readers' release fence),
            // never satisfied from a stale L1 line, not hoistable like __ldg.
            float  si = __ldcg(&src[row]);
            float4 sd = __ldcg(&dst4[((row >> 11) << 9) + j4]);
            float4 o;
            o.x = fmaxf(si + sd.x, 0.f);
            o.y = fmaxf(si + sd.y, 0.f);
            o.z = fmaxf(si + sd.z, 0.f);
            o.w = fmaxf(si + sd.w, 0.f);
            __stcs(&out[v], o);
        }
    }
}

extern "C" void kernel_launch(void* const* d_in, const int* in_sizes, int n_in,
                              void* d_out, int out_size)
{
    const float* H  = (const float*)d_in[0];
    const float* Dh = (const float*)d_in[1];
    const float* W  = (const float*)d_in[2];
    const float* b  = (const float*)d_in[3];
    float4* out = (float4*)d_out;

    edge_reset<<<1, 32>>>();
    edge_fused<<<NBLOCKS, 256>>>(H, Dh, W, b, out);
}

// round 10
// speedup vs baseline: 1.4596x; 1.4596x over previous
#include <cuda_runtime.h>

// Problem constants: B=8, N=2048, D=768, two tensors -> 16 (tensor,batch) groups
#define DDIM     768
#define NROWS    32768          // 2*8*2048 source rows
#define NGROUPS  16             // groups of 2048 rows; 16 MB output per group
#define ROW4     512            // float4 per output row
#define NREADER  256            // reader blocks (bids 0..255, wave-1 resident)
#define NWRITER  16384          // one 16KB chunk per writer block (round-7 shape)
#define NBLOCKS  (NREADER + NWRITER)

__device__ float    g_src[NROWS];
__device__ float    g_dst[NROWS];
__device__ unsigned g_cnt[NGROUPS];   // rows published per group (target 2048)

__global__ void edge_reset() {
    if (threadIdx.x < NGROUPS) g_cnt[threadIdx.x] = 0;
}

__global__ __launch_bounds__(256) void edge_fused(
    const float* __restrict__ H,
    const float* __restrict__ Dh,
    const float* __restrict__ W,     // [2*DDIM]: wa then wb
    const float* __restrict__ bptr,  // [1]
    float4* __restrict__ out)
{
    const int tid = threadIdx.x;
    const int bid = blockIdx.x;

    if (bid < NREADER) {
        // ---------------- Readers: 256 blocks * 8 warps = 2048 warps ----------------
        // Group-major: group g's 2048 rows done at ~(g+1)*1.3us, then published.
        int wid  = tid >> 5;
        int lane = tid & 31;
        const float4* Wa4 = (const float4*)W;
        const float4* Wb4 = (const float4*)(W + DDIM);
        float bias = __ldg(bptr);

        for (int g = 0; g < NGROUPS; g++) {
            int r = g * 2048 + bid * 8 + wid;
            const float* X = (r < NROWS / 2) ? (H  + (size_t)r * DDIM)
                                             : (Dh + (size_t)(r - NROWS / 2) * DDIM);
            const float4* X4 = (const float4*)X;
            float sa = 0.f, sb = 0.f;
            #pragma unroll
            for (int k = 0; k < 6; k++) {
                int idx = lane + k * 32;
                float4 x  = __ldcs(&X4[idx]);
                float4 wa = __ldg(&Wa4[idx]);
                float4 wb = __ldg(&Wb4[idx]);
                sa = fmaf(x.x, wa.x, fmaf(x.y, wa.y, fmaf(x.z, wa.z, fmaf(x.w, wa.w, sa))));
                sb = fmaf(x.x, wb.x, fmaf(x.y, wb.y, fmaf(x.z, wb.z, fmaf(x.w, wb.w, sb))));
            }
            #pragma unroll
            for (int off = 16; off; off >>= 1) {
                sa += __shfl_xor_sync(0xffffffffu, sa, off);
                sb += __shfl_xor_sync(0xffffffffu, sb, off);
            }
            if (lane == 0) {
                g_src[r] = sa + bias;
                g_dst[r] = sb;
                __threadfence();                  // release s-values to L2 before count
                atomicAdd(&g_cnt[g], 1u);
            }
        }
        return;
    }

    // ---------------- Writers: 16384 blocks, ONE contiguous 16KB chunk each ----------
    // Exact round-7 phase-2 store body; single spin before it, no other sync.
    unsigned chunk = (unsigned)(bid - NREADER);   // 0..16383
    unsigned grp   = chunk >> 10;                 // 1024 chunks per group

    if (tid == 0) {
        volatile unsigned* p = &g_cnt[grp];
        while (*p < 2048u) __nanosleep(64);
        __threadfence();                          // acquire
    }
    __syncthreads();                              // loads below cannot hoist above this

    const float*  src  = g_src;
    const float4* dst4 = (const float4*)g_dst;

    unsigned base = chunk * 1024u;                // float4 offset (2 output rows)
    #pragma unroll
    for (int it = 0; it < 4; it++) {
        unsigned v   = base + it * 256u + tid;
        unsigned row = v >> 9;
        unsigned j4  = v & (ROW4 - 1);
        float  si = __ldcg(&src[row]);            // coherent L2 read (fresh post-fence)
        float4 sd = __ldcg(&dst4[((row >> 11) << 9) + j4]);
        float4 o;
        o.x = fmaxf(si + sd.x, 0.f);
        o.y = fmaxf(si + sd.y, 0.f);
        o.z = fmaxf(si + sd.z, 0.f);
        o.w = fmaxf(si + sd.w, 0.f);
        __stcs(&out[v], o);
    }
}

extern "C" void kernel_launch(void* const* d_in, const int* in_sizes, int n_in,
                              void* d_out, int out_size)
{
    const float* H  = (const float*)d_in[0];
    const float* Dh = (const float*)d_in[1];
    const float* W  = (const float*)d_in[2];
    const float* b  = (const float*)d_in[3];
    float4* out = (float4*)d_out;

    edge_reset<<<1, 32>>>();
    edge_fused<<<NBLOCKS, 256>>>(H, Dh, W, b, out);
}

// round 12
// speedup vs baseline: 2.1891x; 1.4998x over previous
#include <cuda_runtime.h>

// Problem constants: B=8, N=2048, D=768, two tensors (H, doc_sents_h)
#define DDIM   768
#define NROWS  32768            // 2 * 8 * 2048 source rows
#define HALF   16384            // rows per tensor
#define ROW4   512              // float4 per output row (2048/4)

// Scratch: s_src (bias folded in) and s_dst per (tensor, batch, n)
__device__ float g_src[NROWS];
__device__ float g_dst[NROWS];

// Phase 1: one warp handles row r of H AND row r of Dh (same weights).
// Doubles per-warp load MLP (12 outstanding x-loads) and halves weight traffic.
__global__ __launch_bounds__(256) void edge_phase1(
    const float* __restrict__ H,
    const float* __restrict__ Dh,
    const float* __restrict__ W,     // [2*DDIM]: wa then wb
    const float* __restrict__ bptr)  // [1]
{
    int r    = blockIdx.x * 8 + (threadIdx.x >> 5);   // pair index 0..16383
    int lane = threadIdx.x & 31;
    if (r >= HALF) return;

    const float4* X4  = (const float4*)(H  + (size_t)r * DDIM);
    const float4* Y4  = (const float4*)(Dh + (size_t)r * DDIM);
    const float4* Wa4 = (const float4*)W;
    const float4* Wb4 = (const float4*)(W + DDIM);

    float sa1 = 0.f, sb1 = 0.f, sa2 = 0.f, sb2 = 0.f;
    #pragma unroll
    for (int k = 0; k < 6; k++) {                     // 192 float4 per row / 32 lanes
        int idx = lane + k * 32;
        float4 x  = __ldcs(&X4[idx]);
        float4 y  = __ldcs(&Y4[idx]);
        float4 wa = __ldg(&Wa4[idx]);
        float4 wb = __ldg(&Wb4[idx]);
        sa1 = fmaf(x.x, wa.x, fmaf(x.y, wa.y, fmaf(x.z, wa.z, fmaf(x.w, wa.w, sa1))));
        sb1 = fmaf(x.x, wb.x, fmaf(x.y, wb.y, fmaf(x.z, wb.z, fmaf(x.w, wb.w, sb1))));
        sa2 = fmaf(y.x, wa.x, fmaf(y.y, wa.y, fmaf(y.z, wa.z, fmaf(y.w, wa.w, sa2))));
        sb2 = fmaf(y.x, wb.x, fmaf(y.y, wb.y, fmaf(y.z, wb.z, fmaf(y.w, wb.w, sb2))));
    }
    #pragma unroll
    for (int off = 16; off; off >>= 1) {
        sa1 += __shfl_xor_sync(0xffffffffu, sa1, off);
        sb1 += __shfl_xor_sync(0xffffffffu, sb1, off);
        sa2 += __shfl_xor_sync(0xffffffffu, sa2, off);
        sb2 += __shfl_xor_sync(0xffffffffu, sb2, off);
    }
    if (lane == 0) {
        float bias = __ldg(bptr);
        g_src[r]        = sa1 + bias;   // H rows -> first half
        g_dst[r]        = sb1;
        g_src[r + HALF] = sa2 + bias;   // Dh rows -> second half
        g_dst[r + HALF] = sb2;
    }
}

// Phase 2 (unchanged from round 7 — at the store-path ceiling):
// each block writes 1024 CONSECUTIVE float4 (16 KB), streaming stores.
__global__ __launch_bounds__(256) void edge_phase2(float4* __restrict__ out)
{
    const float*  __restrict__ src  = g_src;
    const float4* __restrict__ dst4 = (const float4*)g_dst;

    unsigned base = blockIdx.x * 1024u;               // 16384 blocks
    #pragma unroll
    for (int it = 0; it < 4; it++) {
        unsigned v   = base + it * 256u + threadIdx.x;
        unsigned row = v >> 9;                        // /ROW4
        unsigned j4  = v & (ROW4 - 1);
        float  si = __ldg(&src[row]);
        float4 sd = __ldg(&dst4[((row >> 11) << 9) + j4]);  // group = row/2048
        float4 o;
        o.x = fmaxf(si + sd.x, 0.f);
        o.y = fmaxf(si + sd.y, 0.f);
        o.z = fmaxf(si + sd.z, 0.f);
        o.w = fmaxf(si + sd.w, 0.f);
        __stcs(&out[v], o);
    }
}

extern "C" void kernel_launch(void* const* d_in, const int* in_sizes, int n_in,
                              void* d_out, int out_size)
{
    const float* H  = (const float*)d_in[0];
    const float* Dh = (const float*)d_in[1];
    const float* W  = (const float*)d_in[2];
    const float* b  = (const float*)d_in[3];
    float4* out = (float4*)d_out;

    edge_phase1<<<2048, 256>>>(H, Dh, W, b);   // 16384 row-pairs, 8 warps/block
    edge_phase2<<<16384, 256>>>(out);          // contiguous 16 KB per block
}

// round 13
// speedup vs baseline: 2.1998x; 1.0049x over previous
#include <cuda_runtime.h>

// Problem constants: B=8, N=2048, D=768, two tensors (H, doc_sents_h)
#define DDIM   768
#define NROWS  32768            // 2 * 8 * 2048 source rows
#define ROW4   512              // float4 per output row (2048/4)

// Scratch: s_src (bias folded in) and s_dst per (tensor, batch, n)
__device__ float g_src[NROWS];
__device__ float g_dst[NROWS];

// Phase 1 (round-7 shape): one warp per row, both dots in one pass.
__global__ __launch_bounds__(256) void edge_phase1(
    const float* __restrict__ H,
    const float* __restrict__ Dh,
    const float* __restrict__ W,     // [2*DDIM]: wa then wb
    const float* __restrict__ bptr)  // [1]
{
    int r    = blockIdx.x * 8 + (threadIdx.x >> 5);   // row 0..32767
    int lane = threadIdx.x & 31;

    const float* X = (r < NROWS / 2) ? (H  + (size_t)r * DDIM)
                                     : (Dh + (size_t)(r - NROWS / 2) * DDIM);
    const float4* X4  = (const float4*)X;
    const float4* Wa4 = (const float4*)W;
    const float4* Wb4 = (const float4*)(W + DDIM);

    float sa = 0.f, sb = 0.f;
    #pragma unroll
    for (int k = 0; k < 6; k++) {                     // 192 float4 per row / 32 lanes
        int idx = lane + k * 32;
        float4 x  = __ldcs(&X4[idx]);
        float4 wa = __ldg(&Wa4[idx]);
        float4 wb = __ldg(&Wb4[idx]);
        sa = fmaf(x.x, wa.x, fmaf(x.y, wa.y, fmaf(x.z, wa.z, fmaf(x.w, wa.w, sa))));
        sb = fmaf(x.x, wb.x, fmaf(x.y, wb.y, fmaf(x.z, wb.z, fmaf(x.w, wb.w, sb))));
    }
    #pragma unroll
    for (int off = 16; off; off >>= 1) {
        sa += __shfl_xor_sync(0xffffffffu, sa, off);
        sb += __shfl_xor_sync(0xffffffffu, sb, off);
    }
    if (lane == 0) {
        g_src[r] = sa + __ldg(bptr);   // fold bias into the src term
        g_dst[r] = sb;
    }
    // Let the dependent phase-2 grid launch as this block retires.
    cudaTriggerProgrammaticLaunchCompletion();
}

// Phase 2: each block writes 2 consecutive output rows (1024 contiguous
// float4 = 16 KB), which share ONE group -> only 2 unique sd vectors and
// 2 si scalars per thread. Same store addresses/order as the 39.4us kernel.
__global__ __launch_bounds__(256) void edge_phase2(float4* __restrict__ out)
{
    // Block until phase 1's memory is visible (PDL prologue already done).
    cudaGridDependencySynchronize();

    const float*  __restrict__ src  = g_src;
    const float4* __restrict__ dst4 = (const float4*)g_dst;

    unsigned tid  = threadIdx.x;
    unsigned row0 = blockIdx.x * 2u;                  // 2 rows per block
    unsigned g9   = (row0 >> 11) << 9;                // group base (float4 units)

    float  si0 = __ldg(&src[row0]);
    float  si1 = __ldg(&src[row0 + 1]);
    float4 sdA = __ldg(&dst4[g9 + tid]);
    float4 sdB = __ldg(&dst4[g9 + tid + 256]);

    unsigned base = row0 * ROW4;
    float4 o;
    o.x = fmaxf(si0 + sdA.x, 0.f); o.y = fmaxf(si0 + sdA.y, 0.f);
    o.z = fmaxf(si0 + sdA.z, 0.f); o.w = fmaxf(si0 + sdA.w, 0.f);
    __stcs(&out[base + tid], o);
    o.x = fmaxf(si0 + sdB.x, 0.f); o.y = fmaxf(si0 + sdB.y, 0.f);
    o.z = fmaxf(si0 + sdB.z, 0.f); o.w = fmaxf(si0 + sdB.w, 0.f);
    __stcs(&out[base + 256 + tid], o);
    o.x = fmaxf(si1 + sdA.x, 0.f); o.y = fmaxf(si1 + sdA.y, 0.f);
    o.z = fmaxf(si1 + sdA.z, 0.f); o.w = fmaxf(si1 + sdA.w, 0.f);
    __stcs(&out[base + 512 + tid], o);
    o.x = fmaxf(si1 + sdB.x, 0.f); o.y = fmaxf(si1 + sdB.y, 0.f);
    o.z = fmaxf(si1 + sdB.z, 0.f); o.w = fmaxf(si1 + sdB.w, 0.f);
    __stcs(&out[base + 768 + tid], o);
}

extern "C" void kernel_launch(void* const* d_in, const int* in_sizes, int n_in,
                              void* d_out, int out_size)
{
    const float* H  = (const float*)d_in[0];
    const float* Dh = (const float*)d_in[1];
    const float* W  = (const float*)d_in[2];
    const float* b  = (const float*)d_in[3];
    float4* out = (float4*)d_out;

    edge_phase1<<<4096, 256>>>(H, Dh, W, b);   // 32768 rows, 8 warps/block

    // Phase 2 with programmatic dependent launch: overlap launch/prologue
    // with phase 1; cudaGridDependencySynchronize() gates the data reads.
    cudaLaunchConfig_t cfg = {};
    cfg.gridDim  = dim3(16384, 1, 1);
    cfg.blockDim = dim3(256, 1, 1);
    cfg.dynamicSmemBytes = 0;
    cfg.stream = 0;
    cudaLaunchAttribute attr[1];
    attr[0].id = cudaLaunchAttributeProgrammaticStreamSerialization;
    attr[0].val.programmaticStreamSerializationAllowed = 1;
    cfg.attrs = attr;
    cfg.numAttrs = 1;
    cudaLaunchKernelEx(&cfg, edge_phase2, out);
}